// round 6
// baseline (speedup 1.0000x reference)
#include <cuda_runtime.h>
#include <cuda_bf16.h>
#include <math.h>
#include <stdint.h>

#define Bsz 64
#define Lsz 512
#define Esz 512
#define Hsz 1024
#define NG  4096     // gate-interleaved cols: col = h*4+g (0=f,1=i,2=o,3=u)
#define NCTA 128     // persistent CTAs, one 32-col group each

// ---------------- device scratch ----------------
__device__ float g_Xg[(size_t)Lsz * Bsz * NG];
__device__ float g_Wall[(size_t)Esz * NG];          // input-proj weights, gate-interleaved
__device__ float g_ball[NG];
// Wh as mma fragments: [cg 128][kk 64][img 2: hi/lo][lane 32][reg 8] uint32 (bf16x2)
__device__ uint32_t g_Bfrag[(size_t)NCTA * 64 * 2 * 32 * 8];
__device__ volatile unsigned g_done[NCTA];

// ---------------- helpers ----------------
__device__ __forceinline__ unsigned long long ffma2(unsigned long long a,
                                                    unsigned long long b,
                                                    unsigned long long c) {
    unsigned long long d;
    asm("fma.rn.f32x2 %0, %1, %2, %3;" : "=l"(d) : "l"(a), "l"(b), "l"(c));
    return d;
}
__device__ __forceinline__ unsigned long long packdup(float x) {
    unsigned long long r;
    asm("mov.b64 %0, {%1, %1};" : "=l"(r) : "f"(x));
    return r;
}
__device__ __forceinline__ float2 unpack2(unsigned long long v) {
    float2 f;
    asm("mov.b64 {%0, %1}, %2;" : "=f"(f.x), "=f"(f.y) : "l"(v));
    return f;
}
// fp32 pair -> bf16x2 (hi) + bf16x2 (residual lo); low half = first element
__device__ __forceinline__ void cvt_hilo(float2 v, uint32_t& hi, uint32_t& lo) {
    asm("cvt.rn.bf16x2.f32 %0, %1, %2;" : "=r"(hi) : "f"(v.y), "f"(v.x));
    float h0 = __uint_as_float(hi << 16);
    float h1 = __uint_as_float(hi & 0xFFFF0000u);
    asm("cvt.rn.bf16x2.f32 %0, %1, %2;" : "=r"(lo) : "f"(v.y - h1), "f"(v.x - h0));
}
#define MMA16816(d, a, b0, b1)                                              \
    asm volatile(                                                           \
        "mma.sync.aligned.m16n8k16.row.col.f32.bf16.bf16.f32 "              \
        "{%0,%1,%2,%3}, {%4,%5,%6,%7}, {%8,%9}, {%0,%1,%2,%3};"             \
        : "+f"((d)[0]), "+f"((d)[1]), "+f"((d)[2]), "+f"((d)[3])            \
        : "r"((a)[0]), "r"((a)[1]), "r"((a)[2]), "r"((a)[3]),               \
          "r"(b0), "r"(b1))

// ---------------------------------------------------------------------------
// Pack: Wh -> fragment layout (hi/lo bf16), g_Wall fp32 (input rows), bias, flags.
// Launch 8192 x 256 (idx < 2097152).
// ---------------------------------------------------------------------------
__global__ void pack_kernel(const float* __restrict__ Wf, const float* __restrict__ Wi,
                            const float* __restrict__ Wo, const float* __restrict__ Wu,
                            const float* __restrict__ bf, const float* __restrict__ bi,
                            const float* __restrict__ bo, const float* __restrict__ bu)
{
    int idx = blockIdx.x * 256 + threadIdx.x;   // 0 .. 2097151
    // ---- recurrent-weight fragments ----
    {
        int r    = idx & 7;
        int lane = (idx >> 3) & 31;
        int kk   = (idx >> 8) & 63;
        int cg   = idx >> 14;
        int j = r >> 1, half = r & 1;
        int col = cg * 32 + j * 8 + (lane >> 2);
        int h = col >> 2, g = col & 3;
        int kb = kk * 16 + half * 8 + (lane & 3) * 2;
        const float* W = (g == 0) ? Wf : (g == 1) ? Wi : (g == 2) ? Wo : Wu;
        float w0 = W[(size_t)(Esz + kb) * Hsz + h];
        float w1 = W[(size_t)(Esz + kb + 1) * Hsz + h];
        uint32_t hi, lo;
        cvt_hilo(make_float2(w0, w1), hi, lo);
        size_t base = ((size_t)(cg * 64 + kk) * 2) * 256 + lane * 8 + r;
        g_Bfrag[base]       = hi;
        g_Bfrag[base + 256] = lo;
    }
    // ---- input-proj fp32 weights, gate-interleaved ----
    {
        int k = idx >> 12;
        int c = idx & 4095;
        int h = c >> 2, g = c & 3;
        const float* W = (g == 0) ? Wf : (g == 1) ? Wi : (g == 2) ? Wo : Wu;
        g_Wall[idx] = W[(size_t)k * Hsz + h];
    }
    if (idx < NG) {
        int h = idx >> 2, g = idx & 3;
        const float* bb = (g == 0) ? bf : (g == 1) ? bi : (g == 2) ? bo : bu;
        g_ball[idx] = bb[h];
    }
    if (idx < NCTA) g_done[idx] = 0;
}

// ---------------------------------------------------------------------------
// Input projection (R3 FFMA2, known-good): Xg[t][b][c] = (x@Wx)[m][c] + b_all[c]
// ---------------------------------------------------------------------------
__global__ __launch_bounds__(256) void gemm_x_kernel(const float* __restrict__ x)
{
    __shared__ float As[16][128];
    __shared__ float Bs[16][256];

    const int n0 = blockIdx.x * 256;
    const int m0 = blockIdx.y * 128;
    const int tid = threadIdx.x;
    const int tx = tid & 31, ty = tid >> 5;

    unsigned long long acc[8][8];
#pragma unroll
    for (int rp = 0; rp < 8; rp++)
#pragma unroll
        for (int c = 0; c < 8; c++) acc[rp][c] = 0ull;

    const int arow = tid >> 2, akq = tid & 3;
    const int arow2 = (tid + 256) >> 2, akq2 = (tid + 256) & 3;

    {
        float4 a0 = *(const float4*)(x + (size_t)(m0 + arow) * Esz + akq * 4);
        float4 a1 = *(const float4*)(x + (size_t)(m0 + arow2) * Esz + akq2 * 4);
        As[akq * 4 + 0][arow] = a0.x; As[akq * 4 + 1][arow] = a0.y;
        As[akq * 4 + 2][arow] = a0.z; As[akq * 4 + 3][arow] = a0.w;
        As[akq2 * 4 + 0][arow2] = a1.x; As[akq2 * 4 + 1][arow2] = a1.y;
        As[akq2 * 4 + 2][arow2] = a1.z; As[akq2 * 4 + 3][arow2] = a1.w;
#pragma unroll
        for (int i = 0; i < 4; i++) {
            int f = tid + 256 * i;
            int k = f >> 6, c4 = f & 63;
            *(float4*)&Bs[k][c4 * 4] = *(const float4*)(g_Wall + (size_t)k * NG + n0 + c4 * 4);
        }
    }
    __syncthreads();

    for (int kt = 0; kt < Esz; kt += 16) {
        float4 pa0, pa1, pb[4];
        if (kt + 16 < Esz) {
            int ktn = kt + 16;
            pa0 = *(const float4*)(x + (size_t)(m0 + arow) * Esz + ktn + akq * 4);
            pa1 = *(const float4*)(x + (size_t)(m0 + arow2) * Esz + ktn + akq2 * 4);
#pragma unroll
            for (int i = 0; i < 4; i++) {
                int f = tid + 256 * i;
                int k = f >> 6, c4 = f & 63;
                pb[i] = *(const float4*)(g_Wall + (size_t)(ktn + k) * NG + n0 + c4 * 4);
            }
        }
#pragma unroll
        for (int k = 0; k < 16; k++) {
            unsigned long long a_p[8];
#pragma unroll
            for (int rb = 0; rb < 4; rb++) {
                ulonglong2 av = *(const ulonglong2*)&As[k][32 * rb + ty * 4];
                a_p[rb * 2 + 0] = av.x;
                a_p[rb * 2 + 1] = av.y;
            }
            float4 b0 = *(const float4*)&Bs[k][tx * 4];
            float4 b1 = *(const float4*)&Bs[k][128 + tx * 4];
            unsigned long long bd[8] = {packdup(b0.x), packdup(b0.y), packdup(b0.z), packdup(b0.w),
                                        packdup(b1.x), packdup(b1.y), packdup(b1.z), packdup(b1.w)};
#pragma unroll
            for (int rp = 0; rp < 8; rp++)
#pragma unroll
                for (int c = 0; c < 8; c++)
                    acc[rp][c] = ffma2(a_p[rp], bd[c], acc[rp][c]);
        }
        __syncthreads();
        if (kt + 16 < Esz) {
            As[akq * 4 + 0][arow] = pa0.x; As[akq * 4 + 1][arow] = pa0.y;
            As[akq * 4 + 2][arow] = pa0.z; As[akq * 4 + 3][arow] = pa0.w;
            As[akq2 * 4 + 0][arow2] = pa1.x; As[akq2 * 4 + 1][arow2] = pa1.y;
            As[akq2 * 4 + 2][arow2] = pa1.z; As[akq2 * 4 + 3][arow2] = pa1.w;
#pragma unroll
            for (int i = 0; i < 4; i++) {
                int f = tid + 256 * i;
                int k = f >> 6, c4 = f & 63;
                *(float4*)&Bs[k][c4 * 4] = pb[i];
            }
            __syncthreads();
        }
    }

    float4 bias0 = *(const float4*)(g_ball + n0 + tx * 4);
    float4 bias1 = *(const float4*)(g_ball + n0 + 128 + tx * 4);

#pragma unroll
    for (int rp = 0; rp < 8; rp++) {
        float2 q[8];
#pragma unroll
        for (int c = 0; c < 8; c++) q[c] = unpack2(acc[rp][c]);
        int row0 = m0 + 32 * (rp >> 1) + ty * 4 + (rp & 1) * 2;
#pragma unroll
        for (int pr = 0; pr < 2; pr++) {
            int m = row0 + pr;
            int b = m >> 9;
            int t = m & 511;
            float* dst = g_Xg + ((size_t)(t * Bsz + b)) * NG + n0;
            float4 v0, v1;
            if (pr == 0) {
                v0 = make_float4(q[0].x + bias0.x, q[1].x + bias0.y, q[2].x + bias0.z, q[3].x + bias0.w);
                v1 = make_float4(q[4].x + bias1.x, q[5].x + bias1.y, q[6].x + bias1.z, q[7].x + bias1.w);
            } else {
                v0 = make_float4(q[0].y + bias0.x, q[1].y + bias0.y, q[2].y + bias0.z, q[3].y + bias0.w);
                v1 = make_float4(q[4].y + bias1.x, q[5].y + bias1.y, q[6].y + bias1.z, q[7].y + bias1.w);
            }
            *(float4*)(dst + tx * 4) = v0;
            *(float4*)(dst + 128 + tx * 4) = v1;
        }
    }
}

// ---------------------------------------------------------------------------
// Persistent mma.sync recurrence: 128 CTAs x 256 threads, 1 colgroup (32) each.
// 8 warps = 4 m-tiles x 2 K-halves; 3-term bf16 hi/lo split; c in registers.
// ---------------------------------------------------------------------------
__global__ __launch_bounds__(256, 1) void lstm_mma_kernel(
    const float* __restrict__ mask,
    const float* __restrict__ h0, const float* __restrict__ c0,
    float* __restrict__ outh, float* __restrict__ outc)
{
    __shared__ float gbuf[Bsz][32];

    const int tid = threadIdx.x;
    const int lane = tid & 31, wid = tid >> 5;
    const int mi = wid & 3, kh = wid >> 2;
    const int cg = blockIdx.x;

    // pointwise ownership: thread -> (batch pb, 2 h-units)
    const int pb = tid >> 2;
    const int hu = (tid & 3) * 2;
    float cr0 = c0[(size_t)pb * Hsz + cg * 8 + hu];
    float cr1 = c0[(size_t)pb * Hsz + cg * 8 + hu + 1];

    const int row0 = mi * 16 + (lane >> 2);
    const int kofs = (lane & 3) * 2;
    const uint32_t* bbase = g_Bfrag + ((size_t)(cg * 64 + kh * 32) * 2) * 256 + lane * 8;

    for (int t = 0; t < Lsz; t++) {
        if (t > 0) {
            if (tid < NCTA) {
                while (g_done[tid] < (unsigned)t) __nanosleep(20);
            }
            __syncthreads();
        }
        const float* hp = t ? (outh + (size_t)(t - 1) * Hsz) : h0;
        const size_t hstr = t ? (size_t)Lsz * Hsz : (size_t)Hsz;
        const float* hr0 = hp + (size_t)row0 * hstr + kh * 512 + kofs;
        const float* hr1 = hr0 + 8 * hstr;

        float acc[4][4];
#pragma unroll
        for (int j = 0; j < 4; j++)
#pragma unroll
            for (int q = 0; q < 4; q++) acc[j][q] = 0.f;

#pragma unroll 4
        for (int it = 0; it < 32; it++) {
            // A fragments (h) straight from L2
            float2 v0 = __ldcg((const float2*)(hr0 + it * 16));
            float2 v1 = __ldcg((const float2*)(hr1 + it * 16));
            float2 v2 = __ldcg((const float2*)(hr0 + it * 16 + 8));
            float2 v3 = __ldcg((const float2*)(hr1 + it * 16 + 8));
            uint32_t ah[4], al[4];
            cvt_hilo(v0, ah[0], al[0]);
            cvt_hilo(v1, ah[1], al[1]);
            cvt_hilo(v2, ah[2], al[2]);
            cvt_hilo(v3, ah[3], al[3]);
            // B fragments (prepacked, L1-resident)
            const uint32_t* bp = bbase + (size_t)it * 512;
            uint4 bh0 = *(const uint4*)bp;
            uint4 bh1 = *(const uint4*)(bp + 4);
            uint4 bl0 = *(const uint4*)(bp + 256);
            uint4 bl1 = *(const uint4*)(bp + 260);

            MMA16816(acc[0], ah, bh0.x, bh0.y);
            MMA16816(acc[1], ah, bh0.z, bh0.w);
            MMA16816(acc[2], ah, bh1.x, bh1.y);
            MMA16816(acc[3], ah, bh1.z, bh1.w);
            MMA16816(acc[0], ah, bl0.x, bl0.y);
            MMA16816(acc[1], ah, bl0.z, bl0.w);
            MMA16816(acc[2], ah, bl1.x, bl1.y);
            MMA16816(acc[3], ah, bl1.z, bl1.w);
            MMA16816(acc[0], al, bh0.x, bh0.y);
            MMA16816(acc[1], al, bh0.z, bh0.w);
            MMA16816(acc[2], al, bh1.x, bh1.y);
            MMA16816(acc[3], al, bh1.z, bh1.w);
        }

        // K-half reduction through smem staging
        if (kh == 0) {
#pragma unroll
            for (int j = 0; j < 4; j++) {
                int jc = j * 8 + kofs;
                *(float2*)&gbuf[row0][jc]     = make_float2(acc[j][0], acc[j][1]);
                *(float2*)&gbuf[row0 + 8][jc] = make_float2(acc[j][2], acc[j][3]);
            }
        }
        __syncthreads();
        if (kh == 1) {
#pragma unroll
            for (int j = 0; j < 4; j++) {
                int jc = j * 8 + kofs;
                float2 s0 = *(float2*)&gbuf[row0][jc];
                float2 s1 = *(float2*)&gbuf[row0 + 8][jc];
                *(float2*)&gbuf[row0][jc]     = make_float2(s0.x + acc[j][0], s0.y + acc[j][1]);
                *(float2*)&gbuf[row0 + 8][jc] = make_float2(s1.x + acc[j][2], s1.y + acc[j][3]);
            }
        }
        __syncthreads();

        // fused gates / cell update
        {
            const float* xg = g_Xg + ((size_t)t * Bsz + pb) * NG + cg * 32 + (tid & 3) * 8;
            float4 x0 = __ldcg((const float4*)xg);
            float4 x1 = __ldcg((const float4*)(xg + 4));
            float4 g0 = *(const float4*)&gbuf[pb][(tid & 3) * 8];
            float4 g1 = *(const float4*)&gbuf[pb][(tid & 3) * 8 + 4];
            float mk = mask[(size_t)pb * Lsz + t];

            float f0 = 1.f / (1.f + expf(-(x0.x + g0.x)));
            float i0 = 1.f / (1.f + expf(-(x0.y + g0.y)));
            float o0 = 1.f / (1.f + expf(-(x0.z + g0.z)));
            float u0 = tanhf(x0.w + g0.w);
            float nc0 = f0 * cr0 + i0 * u0;
            float nh0 = o0 * tanhf(nc0);
            nh0 *= mk; nc0 *= mk;

            float f1 = 1.f / (1.f + expf(-(x1.x + g1.x)));
            float i1 = 1.f / (1.f + expf(-(x1.y + g1.y)));
            float o1 = 1.f / (1.f + expf(-(x1.z + g1.z)));
            float u1 = tanhf(x1.w + g1.w);
            float nc1 = f1 * cr1 + i1 * u1;
            float nh1 = o1 * tanhf(nc1);
            nh1 *= mk; nc1 *= mk;

            cr0 = nc0; cr1 = nc1;

            size_t oi = ((size_t)pb * Lsz + t) * Hsz + cg * 8 + hu;
            *(float2*)(outh + oi) = make_float2(nh0, nh1);
            *(float2*)(outc + oi) = make_float2(nc0, nc1);
        }
        __threadfence();
        __syncthreads();
        if (tid == 0) g_done[cg] = t + 1;
    }
}

// ---------------------------------------------------------------------------
extern "C" void kernel_launch(void* const* d_in, const int* in_sizes, int n_in,
                              void* d_out, int out_size)
{
    const float* x    = (const float*)d_in[0];
    const float* mask = (const float*)d_in[1];
    const float* Wf   = (const float*)d_in[2];
    const float* bf   = (const float*)d_in[3];
    const float* Wi   = (const float*)d_in[4];
    const float* bi   = (const float*)d_in[5];
    const float* Wo   = (const float*)d_in[6];
    const float* bo   = (const float*)d_in[7];
    const float* Wu   = (const float*)d_in[8];
    const float* bu   = (const float*)d_in[9];
    const float* h0   = (const float*)d_in[10];
    const float* c0   = (const float*)d_in[11];

    float* outh = (float*)d_out;
    float* outc = outh + (size_t)Bsz * Lsz * Hsz;

    pack_kernel<<<8192, 256>>>(Wf, Wi, Wo, Wu, bf, bi, bo, bu);
    gemm_x_kernel<<<dim3(NG / 256, (Bsz * Lsz) / 128), 256>>>(x);
    lstm_mma_kernel<<<NCTA, 256>>>(mask, h0, c0, outh, outc);
}

// round 7
// speedup vs baseline: 1.3574x; 1.3574x over previous
#include <cuda_runtime.h>
#include <cuda_bf16.h>
#include <math.h>
#include <stdint.h>

#define Bsz 64
#define Lsz 512
#define Esz 512
#define Hsz 1024
#define NG  4096     // gate-interleaved cols: col = h*4+g (0=f,1=i,2=o,3=u)
#define NCTA 128     // persistent CTAs, one 32-col group each

// ---------------- device scratch ----------------
__device__ float g_Xg[(size_t)Lsz * Bsz * NG];
__device__ float g_Wall[(size_t)Esz * NG];          // input-proj weights, gate-interleaved
__device__ float g_ball[NG];
// Wh as mma fragments: [cg 128][kk 64][img 2: hi/lo][lane 32][reg 8] uint32 (bf16x2)
__device__ uint32_t g_Bfrag[(size_t)NCTA * 64 * 2 * 32 * 8];
// h pre-split to bf16 hi/lo fragment layout: [parity][k2 512][b 64] {hi_pair, lo_pair}
__device__ uint2 g_hsplit[2][512 * 64];
__device__ unsigned g_cnt;
__device__ volatile unsigned g_step;

// ---------------- helpers ----------------
__device__ __forceinline__ unsigned long long ffma2(unsigned long long a,
                                                    unsigned long long b,
                                                    unsigned long long c) {
    unsigned long long d;
    asm("fma.rn.f32x2 %0, %1, %2, %3;" : "=l"(d) : "l"(a), "l"(b), "l"(c));
    return d;
}
__device__ __forceinline__ unsigned long long packdup(float x) {
    unsigned long long r;
    asm("mov.b64 %0, {%1, %1};" : "=l"(r) : "f"(x));
    return r;
}
__device__ __forceinline__ float2 unpack2(unsigned long long v) {
    float2 f;
    asm("mov.b64 {%0, %1}, %2;" : "=f"(f.x), "=f"(f.y) : "l"(v));
    return f;
}
// fp32 pair -> bf16x2 hi + bf16x2 residual lo; first element in low half
__device__ __forceinline__ void cvt_hilo(float2 v, uint32_t& hi, uint32_t& lo) {
    asm("cvt.rn.bf16x2.f32 %0, %1, %2;" : "=r"(hi) : "f"(v.y), "f"(v.x));
    float h0 = __uint_as_float(hi << 16);
    float h1 = __uint_as_float(hi & 0xFFFF0000u);
    asm("cvt.rn.bf16x2.f32 %0, %1, %2;" : "=r"(lo) : "f"(v.y - h1), "f"(v.x - h0));
}
#define MMA16816(d, a, b0, b1)                                              \
    asm volatile(                                                           \
        "mma.sync.aligned.m16n8k16.row.col.f32.bf16.bf16.f32 "              \
        "{%0,%1,%2,%3}, {%4,%5,%6,%7}, {%8,%9}, {%0,%1,%2,%3};"             \
        : "+f"((d)[0]), "+f"((d)[1]), "+f"((d)[2]), "+f"((d)[3])            \
        : "r"((a)[0]), "r"((a)[1]), "r"((a)[2]), "r"((a)[3]),               \
          "r"(b0), "r"(b1))

// ---------------------------------------------------------------------------
// Pack: Wh fragments (hi/lo), g_Wall fp32, bias, h0 split, sync counters.
// Launch 8192 x 256.
// ---------------------------------------------------------------------------
__global__ void pack_kernel(const float* __restrict__ Wf, const float* __restrict__ Wi,
                            const float* __restrict__ Wo, const float* __restrict__ Wu,
                            const float* __restrict__ bf, const float* __restrict__ bi,
                            const float* __restrict__ bo, const float* __restrict__ bu,
                            const float* __restrict__ h0)
{
    int idx = blockIdx.x * 256 + threadIdx.x;   // 0 .. 2097151
    // ---- recurrent-weight fragments ----
    {
        int r    = idx & 7;
        int lane = (idx >> 3) & 31;
        int kk   = (idx >> 8) & 63;
        int cg   = idx >> 14;
        int j = r >> 1, half = r & 1;
        int col = cg * 32 + j * 8 + (lane >> 2);
        int h = col >> 2, g = col & 3;
        int kb = kk * 16 + half * 8 + (lane & 3) * 2;
        const float* W = (g == 0) ? Wf : (g == 1) ? Wi : (g == 2) ? Wo : Wu;
        float w0 = W[(size_t)(Esz + kb) * Hsz + h];
        float w1 = W[(size_t)(Esz + kb + 1) * Hsz + h];
        uint32_t hi, lo;
        cvt_hilo(make_float2(w0, w1), hi, lo);
        size_t base = ((size_t)(cg * 64 + kk) * 2) * 256 + lane * 8 + r;
        g_Bfrag[base]       = hi;
        g_Bfrag[base + 256] = lo;
    }
    // ---- input-proj fp32 weights, gate-interleaved ----
    {
        int k = idx >> 12;
        int c = idx & 4095;
        int h = c >> 2, g = c & 3;
        const float* W = (g == 0) ? Wf : (g == 1) ? Wi : (g == 2) ? Wo : Wu;
        g_Wall[idx] = W[(size_t)k * Hsz + h];
    }
    if (idx < NG) {
        int h = idx >> 2, g = idx & 3;
        const float* bb = (g == 0) ? bf : (g == 1) ? bi : (g == 2) ? bo : bu;
        g_ball[idx] = bb[h];
    }
    // ---- h0 split (consumed by step 0 at parity 1) ----
    if (idx < 512 * 64) {
        int k2 = idx >> 6, b = idx & 63;
        float2 v = make_float2(h0[(size_t)b * Hsz + 2 * k2],
                               h0[(size_t)b * Hsz + 2 * k2 + 1]);
        uint32_t hi, lo;
        cvt_hilo(v, hi, lo);
        g_hsplit[1][k2 * 64 + b] = make_uint2(hi, lo);
    }
    if (idx == 0) { g_cnt = 0; g_step = 0; }
}

// ---------------------------------------------------------------------------
// Input projection (FFMA2, known-good): Xg[t][b][c] = (x@Wx)[m][c] + b_all[c]
// ---------------------------------------------------------------------------
__global__ __launch_bounds__(256) void gemm_x_kernel(const float* __restrict__ x)
{
    __shared__ float As[16][128];
    __shared__ float Bs[16][256];

    const int n0 = blockIdx.x * 256;
    const int m0 = blockIdx.y * 128;
    const int tid = threadIdx.x;
    const int tx = tid & 31, ty = tid >> 5;

    unsigned long long acc[8][8];
#pragma unroll
    for (int rp = 0; rp < 8; rp++)
#pragma unroll
        for (int c = 0; c < 8; c++) acc[rp][c] = 0ull;

    const int arow = tid >> 2, akq = tid & 3;
    const int arow2 = (tid + 256) >> 2, akq2 = (tid + 256) & 3;

    {
        float4 a0 = *(const float4*)(x + (size_t)(m0 + arow) * Esz + akq * 4);
        float4 a1 = *(const float4*)(x + (size_t)(m0 + arow2) * Esz + akq2 * 4);
        As[akq * 4 + 0][arow] = a0.x; As[akq * 4 + 1][arow] = a0.y;
        As[akq * 4 + 2][arow] = a0.z; As[akq * 4 + 3][arow] = a0.w;
        As[akq2 * 4 + 0][arow2] = a1.x; As[akq2 * 4 + 1][arow2] = a1.y;
        As[akq2 * 4 + 2][arow2] = a1.z; As[akq2 * 4 + 3][arow2] = a1.w;
#pragma unroll
        for (int i = 0; i < 4; i++) {
            int f = tid + 256 * i;
            int k = f >> 6, c4 = f & 63;
            *(float4*)&Bs[k][c4 * 4] = *(const float4*)(g_Wall + (size_t)k * NG + n0 + c4 * 4);
        }
    }
    __syncthreads();

    for (int kt = 0; kt < Esz; kt += 16) {
        float4 pa0, pa1, pb[4];
        if (kt + 16 < Esz) {
            int ktn = kt + 16;
            pa0 = *(const float4*)(x + (size_t)(m0 + arow) * Esz + ktn + akq * 4);
            pa1 = *(const float4*)(x + (size_t)(m0 + arow2) * Esz + ktn + akq2 * 4);
#pragma unroll
            for (int i = 0; i < 4; i++) {
                int f = tid + 256 * i;
                int k = f >> 6, c4 = f & 63;
                pb[i] = *(const float4*)(g_Wall + (size_t)(ktn + k) * NG + n0 + c4 * 4);
            }
        }
#pragma unroll
        for (int k = 0; k < 16; k++) {
            unsigned long long a_p[8];
#pragma unroll
            for (int rb = 0; rb < 4; rb++) {
                ulonglong2 av = *(const ulonglong2*)&As[k][32 * rb + ty * 4];
                a_p[rb * 2 + 0] = av.x;
                a_p[rb * 2 + 1] = av.y;
            }
            float4 b0 = *(const float4*)&Bs[k][tx * 4];
            float4 b1 = *(const float4*)&Bs[k][128 + tx * 4];
            unsigned long long bd[8] = {packdup(b0.x), packdup(b0.y), packdup(b0.z), packdup(b0.w),
                                        packdup(b1.x), packdup(b1.y), packdup(b1.z), packdup(b1.w)};
#pragma unroll
            for (int rp = 0; rp < 8; rp++)
#pragma unroll
                for (int c = 0; c < 8; c++)
                    acc[rp][c] = ffma2(a_p[rp], bd[c], acc[rp][c]);
        }
        __syncthreads();
        if (kt + 16 < Esz) {
            As[akq * 4 + 0][arow] = pa0.x; As[akq * 4 + 1][arow] = pa0.y;
            As[akq * 4 + 2][arow] = pa0.z; As[akq * 4 + 3][arow] = pa0.w;
            As[akq2 * 4 + 0][arow2] = pa1.x; As[akq2 * 4 + 1][arow2] = pa1.y;
            As[akq2 * 4 + 2][arow2] = pa1.z; As[akq2 * 4 + 3][arow2] = pa1.w;
#pragma unroll
            for (int i = 0; i < 4; i++) {
                int f = tid + 256 * i;
                int k = f >> 6, c4 = f & 63;
                *(float4*)&Bs[k][c4 * 4] = pb[i];
            }
            __syncthreads();
        }
    }

    float4 bias0 = *(const float4*)(g_ball + n0 + tx * 4);
    float4 bias1 = *(const float4*)(g_ball + n0 + 128 + tx * 4);

#pragma unroll
    for (int rp = 0; rp < 8; rp++) {
        float2 q[8];
#pragma unroll
        for (int c = 0; c < 8; c++) q[c] = unpack2(acc[rp][c]);
        int row0 = m0 + 32 * (rp >> 1) + ty * 4 + (rp & 1) * 2;
#pragma unroll
        for (int pr = 0; pr < 2; pr++) {
            int m = row0 + pr;
            int b = m >> 9;
            int t = m & 511;
            float* dst = g_Xg + ((size_t)(t * Bsz + b)) * NG + n0;
            float4 v0, v1;
            if (pr == 0) {
                v0 = make_float4(q[0].x + bias0.x, q[1].x + bias0.y, q[2].x + bias0.z, q[3].x + bias0.w);
                v1 = make_float4(q[4].x + bias1.x, q[5].x + bias1.y, q[6].x + bias1.z, q[7].x + bias1.w);
            } else {
                v0 = make_float4(q[0].y + bias0.x, q[1].y + bias0.y, q[2].y + bias0.z, q[3].y + bias0.w);
                v1 = make_float4(q[4].y + bias1.x, q[5].y + bias1.y, q[6].y + bias1.z, q[7].y + bias1.w);
            }
            *(float4*)(dst + tx * 4) = v0;
            *(float4*)(dst + 128 + tx * 4) = v1;
        }
    }
}

// ---------------------------------------------------------------------------
// Persistent mma.sync recurrence v2: pre-split h, pipelined loads, 1-word sync.
// 128 CTAs x 256 thr; CTA = 32 gate-cols; 8 warps = 4 m-tiles x 2 K-halves.
// ---------------------------------------------------------------------------
__global__ __launch_bounds__(256, 1) void lstm_mma_kernel(
    const float* __restrict__ mask, const float* __restrict__ c0,
    float* __restrict__ outh, float* __restrict__ outc)
{
    __shared__ float gbufA[Bsz][36];
    __shared__ float gbufB[Bsz][36];

    const int tid = threadIdx.x;
    const int lane = tid & 31, wid = tid >> 5;
    const int mi = wid & 3, kh = wid >> 2;
    const int cg = blockIdx.x;

    // pointwise ownership: thread -> (batch pb, h pair at cg*8 + hu)
    const int pb = tid >> 2;
    const int hu = (tid & 3) * 2;
    const int k2g = cg * 4 + (tid & 3);      // k2 index this thread produces
    float cr0 = c0[(size_t)pb * Hsz + cg * 8 + hu];
    float cr1 = c0[(size_t)pb * Hsz + cg * 8 + hu + 1];

    const int row0 = mi * 16 + (lane >> 2);
    const int kofs = (lane & 3) * 2;
    const uint32_t* bbase = g_Bfrag + ((size_t)(cg * 64 + kh * 32) * 2) * 256 + lane * 8;
    const int kl = lane & 3;

    for (int t = 0; t < Lsz; t++) {
        if (t > 0) {
            if (tid == 0) {
                while (g_step < (unsigned)t) __nanosleep(32);
            }
            __syncthreads();
        }
        const uint2* hs = g_hsplit[(t + 1) & 1];   // read parity (t-1)&1

        float acc[4][4];
#pragma unroll
        for (int j = 0; j < 4; j++)
#pragma unroll
            for (int q = 0; q < 4; q++) acc[j][q] = 0.f;

        uint2 fA[2][4];
        uint4 fB[2][4];
        auto loadA = [&](int s, int it) {
            const uint2* p = hs + (kh * 256 + it * 8 + kl) * 64 + row0;
            fA[s][0] = __ldcg(p);
            fA[s][1] = __ldcg(p + 8);
            fA[s][2] = __ldcg(p + 256);
            fA[s][3] = __ldcg(p + 264);
        };
        auto loadB = [&](int s, int it) {
            const uint32_t* bp = bbase + (size_t)it * 512;
            fB[s][0] = *(const uint4*)bp;
            fB[s][1] = *(const uint4*)(bp + 4);
            fB[s][2] = *(const uint4*)(bp + 256);
            fB[s][3] = *(const uint4*)(bp + 260);
        };
        loadA(0, 0); loadB(0, 0);
        loadA(1, 1); loadB(1, 1);

#pragma unroll 4
        for (int it = 0; it < 32; it++) {
            const int cur = it & 1;
            uint32_t ah[4], al[4];
#pragma unroll
            for (int j = 0; j < 4; j++) { ah[j] = fA[cur][j].x; al[j] = fA[cur][j].y; }
            uint4 bh0 = fB[cur][0], bh1 = fB[cur][1];
            uint4 bl0 = fB[cur][2], bl1 = fB[cur][3];
            if (it + 2 < 32) { loadA(cur, it + 2); loadB(cur, it + 2); }

            MMA16816(acc[0], ah, bh0.x, bh0.y);
            MMA16816(acc[1], ah, bh0.z, bh0.w);
            MMA16816(acc[2], ah, bh1.x, bh1.y);
            MMA16816(acc[3], ah, bh1.z, bh1.w);
            MMA16816(acc[0], ah, bl0.x, bl0.y);
            MMA16816(acc[1], ah, bl0.z, bl0.w);
            MMA16816(acc[2], ah, bl1.x, bl1.y);
            MMA16816(acc[3], ah, bl1.z, bl1.w);
            MMA16816(acc[0], al, bh0.x, bh0.y);
            MMA16816(acc[1], al, bh0.z, bh0.w);
            MMA16816(acc[2], al, bh1.x, bh1.y);
            MMA16816(acc[3], al, bh1.z, bh1.w);
        }

        // K-half staging (one sync: kh0 -> A, kh1 -> B, pointwise sums)
        {
            float (*gb)[36] = (kh == 0) ? gbufA : gbufB;
#pragma unroll
            for (int j = 0; j < 4; j++) {
                int jc = j * 8 + kofs;
                *(float2*)&gb[row0][jc]     = make_float2(acc[j][0], acc[j][1]);
                *(float2*)&gb[row0 + 8][jc] = make_float2(acc[j][2], acc[j][3]);
            }
        }
        __syncthreads();

        // fused gates / cell update; produce split h for next step
        {
            const int cbase = (tid & 3) * 8;
            const float* xg = g_Xg + ((size_t)t * Bsz + pb) * NG + cg * 32 + cbase;
            float4 x0 = __ldcg((const float4*)xg);
            float4 x1 = __ldcg((const float4*)(xg + 4));
            float4 a0 = *(const float4*)&gbufA[pb][cbase];
            float4 a1 = *(const float4*)&gbufA[pb][cbase + 4];
            float4 b0 = *(const float4*)&gbufB[pb][cbase];
            float4 b1 = *(const float4*)&gbufB[pb][cbase + 4];
            float mk = mask[(size_t)pb * Lsz + t];

            float f0 = 1.f / (1.f + expf(-(x0.x + a0.x + b0.x)));
            float i0 = 1.f / (1.f + expf(-(x0.y + a0.y + b0.y)));
            float o0 = 1.f / (1.f + expf(-(x0.z + a0.z + b0.z)));
            float u0 = tanhf(x0.w + a0.w + b0.w);
            float nc0 = f0 * cr0 + i0 * u0;
            float nh0 = o0 * tanhf(nc0);
            nh0 *= mk; nc0 *= mk;

            float f1 = 1.f / (1.f + expf(-(x1.x + a1.x + b1.x)));
            float i1 = 1.f / (1.f + expf(-(x1.y + a1.y + b1.y)));
            float o1 = 1.f / (1.f + expf(-(x1.z + a1.z + b1.z)));
            float u1 = tanhf(x1.w + a1.w + b1.w);
            float nc1 = f1 * cr1 + i1 * u1;
            float nh1 = o1 * tanhf(nc1);
            nh1 *= mk; nc1 *= mk;

            cr0 = nc0; cr1 = nc1;

            size_t oi = ((size_t)pb * Lsz + t) * Hsz + cg * 8 + hu;
            *(float2*)(outh + oi) = make_float2(nh0, nh1);
            *(float2*)(outc + oi) = make_float2(nc0, nc1);

            uint32_t hi, lo;
            cvt_hilo(make_float2(nh0, nh1), hi, lo);
            g_hsplit[t & 1][k2g * 64 + pb] = make_uint2(hi, lo);
        }
        __threadfence();
        __syncthreads();
        if (tid == 0) {
            unsigned old = atomicAdd(&g_cnt, 1u);
            if (old == 128u * (unsigned)(t + 1) - 1u) g_step = (unsigned)(t + 1);
        }
    }
}

// ---------------------------------------------------------------------------
extern "C" void kernel_launch(void* const* d_in, const int* in_sizes, int n_in,
                              void* d_out, int out_size)
{
    const float* x    = (const float*)d_in[0];
    const float* mask = (const float*)d_in[1];
    const float* Wf   = (const float*)d_in[2];
    const float* bf   = (const float*)d_in[3];
    const float* Wi   = (const float*)d_in[4];
    const float* bi   = (const float*)d_in[5];
    const float* Wo   = (const float*)d_in[6];
    const float* bo   = (const float*)d_in[7];
    const float* Wu   = (const float*)d_in[8];
    const float* bu   = (const float*)d_in[9];
    const float* h0   = (const float*)d_in[10];
    const float* c0   = (const float*)d_in[11];

    float* outh = (float*)d_out;
    float* outc = outh + (size_t)Bsz * Lsz * Hsz;

    pack_kernel<<<8192, 256>>>(Wf, Wi, Wo, Wu, bf, bi, bo, bu, h0);
    gemm_x_kernel<<<dim3(NG / 256, (Bsz * Lsz) / 128), 256>>>(x);
    lstm_mma_kernel<<<NCTA, 256>>>(mask, c0, outh, outc);
}

// round 8
// speedup vs baseline: 1.5928x; 1.1734x over previous
#include <cuda_runtime.h>
#include <cuda_bf16.h>
#include <math.h>
#include <stdint.h>

#define Bsz 64
#define Lsz 512
#define Esz 512
#define Hsz 1024
#define NG  4096     // gate-interleaved cols: col = h*4+g (0=f,1=i,2=o,3=u)
#define NCTA 128     // persistent CTAs for recurrence

// ---------------- device scratch ----------------
__device__ float g_Xg[(size_t)Lsz * Bsz * NG];
__device__ float g_ball[NG];
// Wh fragments: [cg 128][kk 64][img 2: hi/lo][lane 32][reg 8] uint32 (bf16x2)
__device__ uint32_t g_Bfrag[(size_t)NCTA * 64 * 2 * 32 * 8];
// Wx fragments: [nt 512][kk 32][lane 32][4] (r: 0=b0hi 1=b1hi 2=b0lo 3=b1lo)
__device__ uint32_t g_Wxfrag[(size_t)512 * 32 * 32 * 4];
// x fragments:  [mt 2048][kk 32][lane 32][8] (r: 0..3 = a0..a3 hi, 4..7 = lo)
__device__ uint32_t g_Ax[(size_t)2048 * 32 * 32 * 8];
// h pre-split bf16 hi/lo: [parity][k2 512][b 64] {hi_pair, lo_pair}
__device__ uint2 g_hsplit[2][512 * 64];
__device__ unsigned g_cnt;
__device__ volatile unsigned g_step;

// ---------------- helpers ----------------
// fp32 pair -> bf16x2 hi + bf16x2 residual lo; first element in low half
__device__ __forceinline__ void cvt_hilo(float2 v, uint32_t& hi, uint32_t& lo) {
    asm("cvt.rn.bf16x2.f32 %0, %1, %2;" : "=r"(hi) : "f"(v.y), "f"(v.x));
    float h0 = __uint_as_float(hi << 16);
    float h1 = __uint_as_float(hi & 0xFFFF0000u);
    asm("cvt.rn.bf16x2.f32 %0, %1, %2;" : "=r"(lo) : "f"(v.y - h1), "f"(v.x - h0));
}
#define MMA16816(d, a, b0, b1)                                              \
    asm volatile(                                                           \
        "mma.sync.aligned.m16n8k16.row.col.f32.bf16.bf16.f32 "              \
        "{%0,%1,%2,%3}, {%4,%5,%6,%7}, {%8,%9}, {%0,%1,%2,%3};"             \
        : "+f"((d)[0]), "+f"((d)[1]), "+f"((d)[2]), "+f"((d)[3])            \
        : "r"((a)[0]), "r"((a)[1]), "r"((a)[2]), "r"((a)[3]),               \
          "r"(b0), "r"(b1))

// ---------------------------------------------------------------------------
// Pack: Wh fragments, Wx fragments, bias, h0 split, sync counters.
// Launch 8192 x 256 (idx < 2^21).
// ---------------------------------------------------------------------------
__global__ void pack_kernel(const float* __restrict__ Wf, const float* __restrict__ Wi,
                            const float* __restrict__ Wo, const float* __restrict__ Wu,
                            const float* __restrict__ bf, const float* __restrict__ bi,
                            const float* __restrict__ bo, const float* __restrict__ bu,
                            const float* __restrict__ h0)
{
    int idx = blockIdx.x * 256 + threadIdx.x;   // 0 .. 2097151
    // ---- recurrent-weight fragments (hi/lo) ----
    {
        int r    = idx & 7;
        int lane = (idx >> 3) & 31;
        int kk   = (idx >> 8) & 63;
        int cg   = idx >> 14;
        int j = r >> 1, half = r & 1;
        int col = cg * 32 + j * 8 + (lane >> 2);
        int h = col >> 2, g = col & 3;
        int kb = kk * 16 + half * 8 + (lane & 3) * 2;
        const float* W = (g == 0) ? Wf : (g == 1) ? Wi : (g == 2) ? Wo : Wu;
        float w0 = W[(size_t)(Esz + kb) * Hsz + h];
        float w1 = W[(size_t)(Esz + kb + 1) * Hsz + h];
        uint32_t hi, lo;
        cvt_hilo(make_float2(w0, w1), hi, lo);
        size_t base = ((size_t)(cg * 64 + kk) * 2) * 256 + lane * 8 + r;
        g_Bfrag[base]       = hi;
        g_Bfrag[base + 256] = lo;
    }
    // ---- input-projection weight fragments (hi/lo) ----
    {
        int r    = idx & 3;
        int lane = (idx >> 2) & 31;
        int kk   = (idx >> 7) & 31;
        int nt   = idx >> 12;
        int col = nt * 8 + (lane >> 2);
        int h = col >> 2, g = col & 3;
        int k = kk * 16 + (lane & 3) * 2 + (r & 1) * 8;
        const float* W = (g == 0) ? Wf : (g == 1) ? Wi : (g == 2) ? Wo : Wu;
        float w0 = W[(size_t)k * Hsz + h];
        float w1 = W[(size_t)(k + 1) * Hsz + h];
        uint32_t hi, lo;
        cvt_hilo(make_float2(w0, w1), hi, lo);
        g_Wxfrag[idx] = (r >> 1) ? lo : hi;
    }
    if (idx < NG) {
        int h = idx >> 2, g = idx & 3;
        const float* bb = (g == 0) ? bf : (g == 1) ? bi : (g == 2) ? bo : bu;
        g_ball[idx] = bb[h];
    }
    // ---- h0 split (consumed by step 0 at parity 1) ----
    if (idx < 512 * 64) {
        int k2 = idx >> 6, b = idx & 63;
        float2 v = make_float2(h0[(size_t)b * Hsz + 2 * k2],
                               h0[(size_t)b * Hsz + 2 * k2 + 1]);
        uint32_t hi, lo;
        cvt_hilo(v, hi, lo);
        g_hsplit[1][k2 * 64 + b] = make_uint2(hi, lo);
    }
    if (idx == 0) { g_cnt = 0; g_step = 0; }
}

// ---------------------------------------------------------------------------
// Split x into bf16 hi/lo fragment-ordered images. Launch 65536 x 256.
// ---------------------------------------------------------------------------
__global__ void xsplit_kernel(const float* __restrict__ x)
{
    size_t idx = (size_t)blockIdx.x * 256 + threadIdx.x;   // < 16,777,216
    int r    = (int)(idx & 7);
    int lane = (int)((idx >> 3) & 31);
    int kk   = (int)((idx >> 8) & 31);
    int mt   = (int)(idx >> 13);
    int reg = r & 3, img = r >> 2;
    int row = mt * 16 + (lane >> 2) + (reg & 1) * 8;
    int col = kk * 16 + (lane & 3) * 2 + (reg >> 1) * 8;
    float2 v = *(const float2*)(x + (size_t)row * Esz + col);
    uint32_t hi, lo;
    cvt_hilo(v, hi, lo);
    g_Ax[idx] = img ? lo : hi;
}

// ---------------------------------------------------------------------------
// Input projection on mma.sync: Xg[t][b][col] = (x@Wx)[m][col] + bias[col].
// Grid (32 nb, 256 mb), 256 threads, 8 warps = 4m x 2n; warp tile m32 x n64.
// ---------------------------------------------------------------------------
__global__ __launch_bounds__(256, 1) void gemm_x_mma()
{
    const int tid = threadIdx.x;
    const int lane = tid & 31, wid = tid >> 5;
    const int wm = wid & 3, wn = wid >> 2;
    const int nb = blockIdx.x, mb = blockIdx.y;
    const int mt0 = mb * 8 + wm * 2;
    const int nt0 = nb * 16 + wn * 8;

    const uint32_t* abase = g_Ax + ((size_t)mt0 * 32) * 256 + lane * 8;
    const uint32_t* bbase = g_Wxfrag + ((size_t)nt0 * 32) * 128 + lane * 4;

    float acc[2][8][4];
#pragma unroll
    for (int m2 = 0; m2 < 2; m2++)
#pragma unroll
        for (int n = 0; n < 8; n++)
#pragma unroll
            for (int q = 0; q < 4; q++) acc[m2][n][q] = 0.f;

    uint4 fA[2][2][2];
    uint4 fB[2][8];
    auto loadA = [&](int s, int kk) {
#pragma unroll
        for (int m2 = 0; m2 < 2; m2++) {
            const uint32_t* p = abase + (size_t)m2 * 8192 + kk * 256;
            fA[s][m2][0] = *(const uint4*)p;
            fA[s][m2][1] = *(const uint4*)(p + 4);
        }
    };
    auto loadB = [&](int s, int kk) {
#pragma unroll
        for (int n = 0; n < 8; n++)
            fB[s][n] = *(const uint4*)(bbase + (size_t)n * 4096 + kk * 128);
    };
    loadA(0, 0); loadB(0, 0);
    loadA(1, 1); loadB(1, 1);

#pragma unroll 2
    for (int kk = 0; kk < 32; kk++) {
        const int cur = kk & 1;
        uint32_t ah[2][4], al[2][4];
#pragma unroll
        for (int m2 = 0; m2 < 2; m2++) {
            ah[m2][0] = fA[cur][m2][0].x; ah[m2][1] = fA[cur][m2][0].y;
            ah[m2][2] = fA[cur][m2][0].z; ah[m2][3] = fA[cur][m2][0].w;
            al[m2][0] = fA[cur][m2][1].x; al[m2][1] = fA[cur][m2][1].y;
            al[m2][2] = fA[cur][m2][1].z; al[m2][3] = fA[cur][m2][1].w;
        }
        uint4 bv[8];
#pragma unroll
        for (int n = 0; n < 8; n++) bv[n] = fB[cur][n];
        if (kk + 2 < 32) { loadA(cur, kk + 2); loadB(cur, kk + 2); }

#pragma unroll
        for (int m2 = 0; m2 < 2; m2++)
#pragma unroll
            for (int n = 0; n < 8; n++) {
                MMA16816(acc[m2][n], ah[m2], bv[n].x, bv[n].y);
                MMA16816(acc[m2][n], ah[m2], bv[n].z, bv[n].w);
                MMA16816(acc[m2][n], al[m2], bv[n].x, bv[n].y);
            }
    }

    // epilogue: bias + scatter to g_Xg[t][b][col]
#pragma unroll
    for (int m2 = 0; m2 < 2; m2++) {
        int m = mb * 128 + wm * 32 + m2 * 16 + (lane >> 2);
        int b = m >> 9, t = m & 511;                 // rows m and m+8 share b
        float* d0 = g_Xg + ((size_t)(t * Bsz + b)) * NG;
        float* d1 = g_Xg + ((size_t)((t + 8) * Bsz + b)) * NG;
#pragma unroll
        for (int n = 0; n < 8; n++) {
            int col = nb * 128 + wn * 64 + n * 8 + (lane & 3) * 2;
            float2 bias = *(const float2*)(g_ball + col);
            *(float2*)(d0 + col) = make_float2(acc[m2][n][0] + bias.x,
                                               acc[m2][n][1] + bias.y);
            *(float2*)(d1 + col) = make_float2(acc[m2][n][2] + bias.x,
                                               acc[m2][n][3] + bias.y);
        }
    }
}

// ---------------------------------------------------------------------------
// Persistent mma.sync recurrence (R7, banked): pre-split h, pipelined loads.
// ---------------------------------------------------------------------------
__global__ __launch_bounds__(256, 1) void lstm_mma_kernel(
    const float* __restrict__ mask, const float* __restrict__ c0,
    float* __restrict__ outh, float* __restrict__ outc)
{
    __shared__ float gbufA[Bsz][36];
    __shared__ float gbufB[Bsz][36];

    const int tid = threadIdx.x;
    const int lane = tid & 31, wid = tid >> 5;
    const int mi = wid & 3, kh = wid >> 2;
    const int cg = blockIdx.x;

    const int pb = tid >> 2;
    const int hu = (tid & 3) * 2;
    const int k2g = cg * 4 + (tid & 3);
    float cr0 = c0[(size_t)pb * Hsz + cg * 8 + hu];
    float cr1 = c0[(size_t)pb * Hsz + cg * 8 + hu + 1];

    const int row0 = mi * 16 + (lane >> 2);
    const int kofs = (lane & 3) * 2;
    const uint32_t* bbase = g_Bfrag + ((size_t)(cg * 64 + kh * 32) * 2) * 256 + lane * 8;
    const int kl = lane & 3;

    for (int t = 0; t < Lsz; t++) {
        if (t > 0) {
            if (tid == 0) {
                while (g_step < (unsigned)t) __nanosleep(32);
            }
            __syncthreads();
        }
        const uint2* hs = g_hsplit[(t + 1) & 1];

        float acc[4][4];
#pragma unroll
        for (int j = 0; j < 4; j++)
#pragma unroll
            for (int q = 0; q < 4; q++) acc[j][q] = 0.f;

        uint2 fA[2][4];
        uint4 fB[2][4];
        auto loadA = [&](int s, int it) {
            const uint2* p = hs + (kh * 256 + it * 8 + kl) * 64 + row0;
            fA[s][0] = __ldcg(p);
            fA[s][1] = __ldcg(p + 8);
            fA[s][2] = __ldcg(p + 256);
            fA[s][3] = __ldcg(p + 264);
        };
        auto loadB = [&](int s, int it) {
            const uint32_t* bp = bbase + (size_t)it * 512;
            fB[s][0] = *(const uint4*)bp;
            fB[s][1] = *(const uint4*)(bp + 4);
            fB[s][2] = *(const uint4*)(bp + 256);
            fB[s][3] = *(const uint4*)(bp + 260);
        };
        loadA(0, 0); loadB(0, 0);
        loadA(1, 1); loadB(1, 1);

#pragma unroll 4
        for (int it = 0; it < 32; it++) {
            const int cur = it & 1;
            uint32_t ah[4], al[4];
#pragma unroll
            for (int j = 0; j < 4; j++) { ah[j] = fA[cur][j].x; al[j] = fA[cur][j].y; }
            uint4 bh0 = fB[cur][0], bh1 = fB[cur][1];
            uint4 bl0 = fB[cur][2], bl1 = fB[cur][3];
            if (it + 2 < 32) { loadA(cur, it + 2); loadB(cur, it + 2); }

            MMA16816(acc[0], ah, bh0.x, bh0.y);
            MMA16816(acc[1], ah, bh0.z, bh0.w);
            MMA16816(acc[2], ah, bh1.x, bh1.y);
            MMA16816(acc[3], ah, bh1.z, bh1.w);
            MMA16816(acc[0], ah, bl0.x, bl0.y);
            MMA16816(acc[1], ah, bl0.z, bl0.w);
            MMA16816(acc[2], ah, bl1.x, bl1.y);
            MMA16816(acc[3], ah, bl1.z, bl1.w);
            MMA16816(acc[0], al, bh0.x, bh0.y);
            MMA16816(acc[1], al, bh0.z, bh0.w);
            MMA16816(acc[2], al, bh1.x, bh1.y);
            MMA16816(acc[3], al, bh1.z, bh1.w);
        }

        {
            float (*gb)[36] = (kh == 0) ? gbufA : gbufB;
#pragma unroll
            for (int j = 0; j < 4; j++) {
                int jc = j * 8 + kofs;
                *(float2*)&gb[row0][jc]     = make_float2(acc[j][0], acc[j][1]);
                *(float2*)&gb[row0 + 8][jc] = make_float2(acc[j][2], acc[j][3]);
            }
        }
        __syncthreads();

        {
            const int cbase = (tid & 3) * 8;
            const float* xg = g_Xg + ((size_t)t * Bsz + pb) * NG + cg * 32 + cbase;
            float4 x0 = __ldcg((const float4*)xg);
            float4 x1 = __ldcg((const float4*)(xg + 4));
            float4 a0 = *(const float4*)&gbufA[pb][cbase];
            float4 a1 = *(const float4*)&gbufA[pb][cbase + 4];
            float4 b0 = *(const float4*)&gbufB[pb][cbase];
            float4 b1 = *(const float4*)&gbufB[pb][cbase + 4];
            float mk = mask[(size_t)pb * Lsz + t];

            float f0 = 1.f / (1.f + expf(-(x0.x + a0.x + b0.x)));
            float i0 = 1.f / (1.f + expf(-(x0.y + a0.y + b0.y)));
            float o0 = 1.f / (1.f + expf(-(x0.z + a0.z + b0.z)));
            float u0 = tanhf(x0.w + a0.w + b0.w);
            float nc0 = f0 * cr0 + i0 * u0;
            float nh0 = o0 * tanhf(nc0);
            nh0 *= mk; nc0 *= mk;

            float f1 = 1.f / (1.f + expf(-(x1.x + a1.x + b1.x)));
            float i1 = 1.f / (1.f + expf(-(x1.y + a1.y + b1.y)));
            float o1 = 1.f / (1.f + expf(-(x1.z + a1.z + b1.z)));
            float u1 = tanhf(x1.w + a1.w + b1.w);
            float nc1 = f1 * cr1 + i1 * u1;
            float nh1 = o1 * tanhf(nc1);
            nh1 *= mk; nc1 *= mk;

            cr0 = nc0; cr1 = nc1;

            size_t oi = ((size_t)pb * Lsz + t) * Hsz + cg * 8 + hu;
            *(float2*)(outh + oi) = make_float2(nh0, nh1);
            *(float2*)(outc + oi) = make_float2(nc0, nc1);

            uint32_t hi, lo;
            cvt_hilo(make_float2(nh0, nh1), hi, lo);
            g_hsplit[t & 1][k2g * 64 + pb] = make_uint2(hi, lo);
        }
        __threadfence();
        __syncthreads();
        if (tid == 0) {
            unsigned old = atomicAdd(&g_cnt, 1u);
            if (old == 128u * (unsigned)(t + 1) - 1u) g_step = (unsigned)(t + 1);
        }
    }
}

// ---------------------------------------------------------------------------
extern "C" void kernel_launch(void* const* d_in, const int* in_sizes, int n_in,
                              void* d_out, int out_size)
{
    const float* x    = (const float*)d_in[0];
    const float* mask = (const float*)d_in[1];
    const float* Wf   = (const float*)d_in[2];
    const float* bf   = (const float*)d_in[3];
    const float* Wi   = (const float*)d_in[4];
    const float* bi   = (const float*)d_in[5];
    const float* Wo   = (const float*)d_in[6];
    const float* bo   = (const float*)d_in[7];
    const float* Wu   = (const float*)d_in[8];
    const float* bu   = (const float*)d_in[9];
    const float* h0   = (const float*)d_in[10];
    const float* c0   = (const float*)d_in[11];

    float* outh = (float*)d_out;
    float* outc = outh + (size_t)Bsz * Lsz * Hsz;

    pack_kernel<<<8192, 256>>>(Wf, Wi, Wo, Wu, bf, bi, bo, bu, h0);
    xsplit_kernel<<<65536, 256>>>(x);
    gemm_x_mma<<<dim3(32, 256), 256>>>();
    lstm_mma_kernel<<<NCTA, 256>>>(mask, c0, outh, outc);
}